// round 9
// baseline (speedup 1.0000x reference)
#include <cuda_runtime.h>
#include <cuda_fp16.h>
#include <math.h>
#include <cstddef>

// ---------------------------------------------------------------------------
// Problem constants
// ---------------------------------------------------------------------------
namespace {
constexpr int BATCH = 4, HGT = 96, WID = 96, CH = 384, HDIM = 128;
constexpr int NPIX = BATCH * HGT * WID;   // 36864
constexpr int NPAD = NPIX + 128;
constexpr int MLPH = 4 * CH;              // 1536
constexpr float ATTN_SCALE = 0.15430334996209191f; // (128//3)^-0.5
constexpr int ATTN_SMEM_BYTES = (3 * 96 * 132 + 96 * 100) * 4;        // 190464
// conv: A [2][32][136]h + W [2][64][136]h
constexpr int CONVH_SMEM_BYTES = (2 * 32 * 136 + 2 * 64 * 136) * 2;   // 52224
// gemm: A [2][128][40]h + B [2][32][136]h
constexpr int GH_SMEM_BYTES = (2 * 128 * 40 + 2 * 32 * 136) * 2;      // 37888
}

// ---------------------------------------------------------------------------
// Scratch (device globals)
// ---------------------------------------------------------------------------
__device__ float g_gates[NPIX * 6];
__device__ float g_qkv[(size_t)NPIX * 3 * HDIM];
__device__ float g_xc[(size_t)NPAD * CH];
__device__ float g_mgate[NPAD * 3];
__device__ float g_accum[(size_t)NPAD * CH];
__device__ int g_midx[3 * NPAD];
__device__ int g_cnt[3];
__device__ int g_cntp[3];
// fp16 tensors
__device__ __half g_xh[(size_t)NPIX * CH];
__device__ __half g_wch[6 * 9 * 128 * 128];
__device__ __half g_wqkvh[3 * 128 * 384];
__device__ __half g_waph[3 * 128 * 128];
__device__ __half g_w1h[(size_t)3 * 384 * 1536];
__device__ __half g_w2h[(size_t)3 * 1536 * 384];
__device__ __half g_wph[384 * 384];
__device__ __half g_moeh[(size_t)NPIX * HDIM];
__device__ __half g_obufh[(size_t)NPIX * HDIM];
__device__ __half g_xch[(size_t)NPAD * CH];
__device__ __half g_hiddenh[(size_t)NPAD * MLPH];
__device__ __half g_accumh[(size_t)NPAD * CH];

__device__ __forceinline__ float gelu_f(float v) {
    float u = 0.7978845608028654f * (v + 0.044715f * v * v * v);
    return 0.5f * v * (1.0f + tanhf(u));
}

// ---------------------------------------------------------------------------
// PTX helpers
// ---------------------------------------------------------------------------
__device__ __forceinline__ unsigned smem_u32p(const void* p) {
    return (unsigned)__cvta_generic_to_shared(p);
}
__device__ __forceinline__ void cp16(const void* dst, const void* src) {
    asm volatile("cp.async.cg.shared.global [%0],[%1],16;"
                 :: "r"(smem_u32p(dst)), "l"(src));
}
__device__ __forceinline__ void cp16z(const void* dst, const void* src, int sz) {
    asm volatile("cp.async.cg.shared.global [%0],[%1],16,%2;"
                 :: "r"(smem_u32p(dst)), "l"(src), "r"(sz));
}
__device__ __forceinline__ void cp_commit() {
    asm volatile("cp.async.commit_group;");
}
template <int N>
__device__ __forceinline__ void cp_wait() {
    asm volatile("cp.async.wait_group %0;" :: "n"(N));
}
// fp16 m16n8k16 mma, fp32 accum
__device__ __forceinline__ void mma16(float* c, const unsigned* a, const unsigned* b) {
    asm volatile(
        "mma.sync.aligned.m16n8k16.row.col.f32.f16.f16.f32 "
        "{%0,%1,%2,%3}, {%4,%5,%6,%7}, {%8,%9}, {%0,%1,%2,%3};"
        : "+f"(c[0]), "+f"(c[1]), "+f"(c[2]), "+f"(c[3])
        : "r"(a[0]), "r"(a[1]), "r"(a[2]), "r"(a[3]), "r"(b[0]), "r"(b[1]));
}
// tf32 m16n8k8 (attention only)
__device__ __forceinline__ void mma8(float* c, const float* a, const float* b) {
    asm volatile(
        "mma.sync.aligned.m16n8k8.row.col.f32.tf32.tf32.f32 "
        "{%0,%1,%2,%3}, {%4,%5,%6,%7}, {%8,%9}, {%0,%1,%2,%3};"
        : "+f"(c[0]), "+f"(c[1]), "+f"(c[2]), "+f"(c[3])
        : "r"(__float_as_uint(a[0])), "r"(__float_as_uint(a[1])),
          "r"(__float_as_uint(a[2])), "r"(__float_as_uint(a[3])),
          "r"(__float_as_uint(b[0])), "r"(__float_as_uint(b[1])));
}
__device__ __forceinline__ void ldsm_x4(unsigned* r, unsigned addr) {
    asm volatile("ldmatrix.sync.aligned.m8n8.x4.shared.b16 {%0,%1,%2,%3},[%4];"
                 : "=r"(r[0]), "=r"(r[1]), "=r"(r[2]), "=r"(r[3]) : "r"(addr));
}
__device__ __forceinline__ void ldsm_x4t(unsigned* r, unsigned addr) {
    asm volatile("ldmatrix.sync.aligned.m8n8.x4.trans.shared.b16 {%0,%1,%2,%3},[%4];"
                 : "=r"(r[0]), "=r"(r[1]), "=r"(r[2]), "=r"(r[3]) : "r"(addr));
}

// ---------------------------------------------------------------------------
// fp32 -> fp16 conversion (RN)
// ---------------------------------------------------------------------------
__global__ __launch_bounds__(256) void f2h_kernel(
    const float* __restrict__ s, __half* __restrict__ d, int n4) {
    int i = blockIdx.x * blockDim.x + threadIdx.x;
    if (i >= n4) return;
    float4 v = ((const float4*)s)[i];
    __half2* dp = (__half2*)d + i * 2;
    dp[0] = __floats2half2_rn(v.x, v.y);
    dp[1] = __floats2half2_rn(v.z, v.w);
}

// ---------------------------------------------------------------------------
// Branch gating (warp per pixel)
// ---------------------------------------------------------------------------
__device__ __forceinline__ void bg_dot(const float* xp, const float* wg, int lane,
                                       float& g0, float& g1) {
    float a0 = 0.f, a1 = 0.f;
#pragma unroll
    for (int i = 0; i < 4; i++) {
        int c = i * 32 + lane;
        float xv = xp[c];
        a0 += xv * wg[c * 2 + 0];
        a1 += xv * wg[c * 2 + 1];
    }
#pragma unroll
    for (int o = 16; o > 0; o >>= 1) {
        a0 += __shfl_xor_sync(0xffffffffu, a0, o);
        a1 += __shfl_xor_sync(0xffffffffu, a1, o);
    }
    float m = fmaxf(a0, a1);
    float e0 = expf(a0 - m), e1 = expf(a1 - m);
    float inv = 1.0f / (e0 + e1);
    g0 = e0 * inv;
    g1 = e1 * inv;
}

__global__ __launch_bounds__(256) void branch_gate_kernel(
    const float* __restrict__ x, const float* __restrict__ wg1,
    const float* __restrict__ wg2, const float* __restrict__ wg3,
    float* __restrict__ gates) {
    int gid = blockIdx.x * blockDim.x + threadIdx.x;
    int pix = gid >> 5;
    int lane = gid & 31;
    if (pix >= NPIX) return;
    const float* xp = x + (size_t)pix * CH;
    float g0, g1;
    bg_dot(xp + 0 * HDIM, wg1, lane, g0, g1);
    if (lane == 0) { gates[pix * 6 + 0] = g0; gates[pix * 6 + 1] = g1; }
    bg_dot(xp + 1 * HDIM, wg2, lane, g0, g1);
    if (lane == 0) { gates[pix * 6 + 2] = g0; gates[pix * 6 + 3] = g1; }
    bg_dot(xp + 2 * HDIM, wg3, lane, g0, g1);
    if (lane == 0) { gates[pix * 6 + 4] = g0; gates[pix * 6 + 5] = g1; }
}

// ---------------------------------------------------------------------------
// Fused dual-conv + gate, fp16 mma (m16n8k16), cp.async pipelined.
// A [32 pix][128 ch] fp16 (x pre-converted), W per-tap fp16.
// 36 steps = 18 taps x 2 K-chunks of 64. Warp tile 32x16.
// ---------------------------------------------------------------------------
__global__ __launch_bounds__(256) void conv_moe_h(
    const __half* __restrict__ xh,
    const __half* __restrict__ wa, const float* __restrict__ ba,
    const __half* __restrict__ wb, const float* __restrict__ bb,
    const float* __restrict__ gates, int br, __half* __restrict__ moeh) {
    extern __shared__ __half chs[];
    __half* sA = chs;                    // [2][32*136]
    __half* sW = chs + 2 * 32 * 136;     // [2][64*136]
    __shared__ float sGA[32], sGB[32];

    int tid = threadIdx.x;
    int lane = tid & 31, wid = tid >> 5;
    int gid = lane >> 2, tig = lane & 3;
    int wn = wid * 16;

    int wc = blockIdx.x % 3;
    int h = blockIdx.x / 3;
    int b = blockIdx.y;
    int w0 = wc * 32;
    int pixbase = (b * HGT + h) * WID + w0;

    if (tid < 32) {
        sGA[tid] = gates[(size_t)(pixbase + tid) * 6 + br * 2 + 0];
        sGB[tid] = gates[(size_t)(pixbase + tid) * 6 + br * 2 + 1];
    }

    auto geo = [&](int t, int& dh, int& dw) {
        int tc = t % 9;
        int isB = (t >= 9);
        if (br == 0)      { dh = tc / 3 - 1; dw = tc % 3 - 1; }
        else if (br == 1) { dh = tc - 4;     dw = 0;          }
        else              { dh = 0;          dw = tc - 4;     }
        if (isB) { dh *= 2; dw *= 2; }
    };

    auto loadA = [&](int t, int buf) {
        int dh, dw;
        geo(t, dh, dw);
        int hh = h + dh;
        __half* dstb = sA + buf * (32 * 136);
#pragma unroll
        for (int l = 0; l < 2; l++) {
            int f = tid + l * 256;          // 0..511
            int p = f >> 4;                 // pixel 0..31
            int c8 = (f & 15) * 8;          // 0..120
            int wv = w0 + p + dw;
            bool ok = (hh >= 0 && hh < HGT && wv >= 0 && wv < WID);
            const __half* src = ok
                ? &xh[((size_t)((b * HGT + hh) * WID + wv)) * CH + br * HDIM + c8]
                : xh;
            cp16z(dstb + p * 136 + c8, src, ok ? 16 : 0);
        }
    };

    auto loadW = [&](int s, int buf) {
        int t = s >> 1, chunk = s & 1;
        int tc = t % 9;
        const __half* wt = ((t >= 9) ? wb : wa) + (size_t)tc * (HDIM * HDIM);
        __half* dstb = sW + buf * (64 * 136);
#pragma unroll
        for (int l = 0; l < 4; l++) {
            int f = tid + l * 256;          // 0..1023
            int k = f >> 4;                 // 0..63
            int c8 = (f & 15) * 8;
            cp16(dstb + k * 136 + c8, &wt[(size_t)(chunk * 64 + k) * HDIM + c8]);
        }
    };

    loadA(0, 0);
    loadW(0, 0);
    cp_commit();

    float accA[2][2][4] = {};
    float accB[2][2][4] = {};

    for (int s = 0; s < 36; s++) {
        int tap = s >> 1;
        if (s + 1 < 36) loadW(s + 1, (s + 1) & 1);
        if ((s & 1) == 0 && tap + 1 < 18) loadA(tap + 1, (tap + 1) & 1);
        cp_commit();
        cp_wait<1>();
        __syncthreads();

        const __half* Ac = sA + (tap & 1) * (32 * 136);
        const __half* Wc = sW + (s & 1) * (64 * 136);
        int kgb = (s & 1) * 64;
        float (*acc)[2][4] = (tap < 9) ? accA : accB;

#pragma unroll
        for (int kk = 0; kk < 64; kk += 16) {
            unsigned a[2][4], bq[4];
#pragma unroll
            for (int mi = 0; mi < 2; mi++) {
                int r = mi * 16 + (lane & 15);
                int c = kgb + kk + (lane >> 4) * 8;
                ldsm_x4(a[mi], smem_u32p(Ac + r * 136 + c));
            }
            {
                int kr = kk + (lane & 15);
                int c = wn + (lane >> 4) * 8;
                ldsm_x4t(bq, smem_u32p(Wc + kr * 136 + c));
            }
#pragma unroll
            for (int mi = 0; mi < 2; mi++)
#pragma unroll
                for (int ni = 0; ni < 2; ni++)
                    mma16(acc[mi][ni], a[mi], &bq[ni * 2]);
        }
        __syncthreads();
    }

    // epilogue: moe = gA*(accA+ba) + gB*(accB+bb), stored fp16
#pragma unroll
    for (int mi = 0; mi < 2; mi++) {
#pragma unroll
        for (int half = 0; half < 2; half++) {
            int p = mi * 16 + gid + half * 8;
            float gg0 = sGA[p], gg1 = sGB[p];
#pragma unroll
            for (int ni = 0; ni < 2; ni++) {
                int c = wn + ni * 8 + tig * 2;
                float v0 = gg0 * (accA[mi][ni][half * 2 + 0] + ba[c]) +
                           gg1 * (accB[mi][ni][half * 2 + 0] + bb[c]);
                float v1 = gg0 * (accA[mi][ni][half * 2 + 1] + ba[c + 1]) +
                           gg1 * (accB[mi][ni][half * 2 + 1] + bb[c + 1]);
                *(__half2*)&moeh[(size_t)(pixbase + p) * HDIM + c] =
                    __floats2half2_rn(v0, v1);
            }
        }
    }
}

// ---------------------------------------------------------------------------
// fp16 tensor-core GEMM, cp.async 2-stage, ldmatrix fragments.
// BM=BN=128, BK=32, warp tile 64x32. Optional gather/scatter via map,
// dual fp32/fp16 outputs, bias/gelu/rowscale/accumulate.
// ---------------------------------------------------------------------------
__global__ __launch_bounds__(256, 2) void gemm_h(
    const __half* __restrict__ A, int lda,
    const __half* __restrict__ B, int ldb,
    const float* __restrict__ bias,
    const float* __restrict__ rowscale, int rs_stride, int rs_off,
    float* __restrict__ Cf, __half* __restrict__ Ch, int ldc,
    int K, int doGelu, int doAccum,
    const int* __restrict__ map, int mapA, const int* __restrict__ cntp) {
    extern __shared__ __half hsm[];
    __half* sA = hsm;                    // [2][128*40]
    __half* sB = hsm + 2 * 128 * 40;     // [2][32*136]
    __shared__ int sMap[128];

    int tid = threadIdx.x;
    int m0 = blockIdx.y * 128, n0 = blockIdx.x * 128;
    if (cntp && m0 >= *cntp) return;

    int lane = tid & 31, wid = tid >> 5;
    int gid = lane >> 2, tig = lane & 3;
    int wm = (wid >> 2) * 64, wn = (wid & 3) * 32;

    if (map) {
        if (tid < 128) sMap[tid] = map[m0 + tid];
        __syncthreads();
    }

    auto loadA = [&](int k0, __half* dst) {
#pragma unroll
        for (int l = 0; l < 2; l++) {
            int f = tid + l * 256;          // 0..511
            int r = f >> 2;                 // 0..127
            int c8 = (f & 3) * 8;           // 0..24
            int ar = (map && mapA) ? sMap[r] : (m0 + r);
            cp16(dst + r * 40 + c8, &A[(size_t)ar * lda + k0 + c8]);
        }
    };
    auto loadB = [&](int k0, __half* dst) {
#pragma unroll
        for (int l = 0; l < 2; l++) {
            int f = tid + l * 256;
            int r = f >> 4;                 // 0..31
            int c8 = (f & 15) * 8;
            cp16(dst + r * 136 + c8, &B[(size_t)(k0 + r) * ldb + n0 + c8]);
        }
    };

    int nk = K / 32;
    loadA(0, sA);
    loadB(0, sB);
    cp_commit();

    float acc[4][4][4] = {};

    for (int i = 0; i < nk; i++) {
        if (i + 1 < nk) {
            loadA((i + 1) * 32, sA + ((i + 1) & 1) * (128 * 40));
            loadB((i + 1) * 32, sB + ((i + 1) & 1) * (32 * 136));
        }
        cp_commit();
        cp_wait<1>();
        __syncthreads();

        const __half* Ac = sA + (i & 1) * (128 * 40);
        const __half* Bc = sB + (i & 1) * (32 * 136);
#pragma unroll
        for (int kk = 0; kk < 32; kk += 16) {
            unsigned a[4][4], bq[2][4];
#pragma unroll
            for (int mi = 0; mi < 4; mi++) {
                int r = wm + mi * 16 + (lane & 15);
                int c = kk + (lane >> 4) * 8;
                ldsm_x4(a[mi], smem_u32p(Ac + r * 40 + c));
            }
#pragma unroll
            for (int p = 0; p < 2; p++) {
                int kr = kk + (lane & 15);
                int c = wn + p * 16 + (lane >> 4) * 8;
                ldsm_x4t(bq[p], smem_u32p(Bc + kr * 136 + c));
            }
#pragma unroll
            for (int mi = 0; mi < 4; mi++)
#pragma unroll
                for (int ni = 0; ni < 4; ni++)
                    mma16(acc[mi][ni], a[mi], &bq[ni >> 1][(ni & 1) * 2]);
        }
        __syncthreads();
    }

    // epilogue
#pragma unroll
    for (int mi = 0; mi < 4; mi++) {
#pragma unroll
        for (int half = 0; half < 2; half++) {
            int rt = wm + mi * 16 + gid + half * 8;
            int cr = (map && !mapA) ? sMap[rt] : (m0 + rt);
            float scl = rowscale ? rowscale[(size_t)cr * rs_stride + rs_off] : 1.0f;
#pragma unroll
            for (int ni = 0; ni < 4; ni++) {
                int c = n0 + wn + ni * 8 + tig * 2;
                float v0 = acc[mi][ni][half * 2 + 0];
                float v1 = acc[mi][ni][half * 2 + 1];
                if (bias) { v0 += bias[c]; v1 += bias[c + 1]; }
                if (doGelu) { v0 = gelu_f(v0); v1 = gelu_f(v1); }
                v0 *= scl; v1 *= scl;
                if (Cf) {
                    float2* cp = (float2*)&Cf[(size_t)cr * ldc + c];
                    if (doAccum) {
                        float2 o = *cp;
                        v0 += o.x; v1 += o.y;
                    }
                    *cp = make_float2(v0, v1);
                }
                if (Ch) {
                    *(__half2*)&Ch[(size_t)cr * ldc + c] = __floats2half2_rn(v0, v1);
                }
            }
        }
    }
}

// ---------------------------------------------------------------------------
// Attention (tf32 mma.sync) — reads fp32 qkv, writes fp16 obuf
// ---------------------------------------------------------------------------
__global__ __launch_bounds__(256) void attn_tc(
    const float* __restrict__ qkv, __half* __restrict__ obufh) {
    extern __shared__ float sm[];
    float* Qs = sm;                    // [96][132]
    float* Ks = sm + 96 * 132;
    float* Vs = sm + 2 * 96 * 132;
    float* Ss = sm + 3 * 96 * 132;     // [96][100]

    int bh = blockIdx.x;
    int b = bh / 96, h = bh % 96;
    int tid = threadIdx.x;
    int lane = tid & 31, wid = tid >> 5;
    int gid = lane >> 2, tig = lane & 3;
    const float* base = qkv + (size_t)bh * 96 * 384;

    for (int f = tid; f < 96 * 96; f += 256) {
        int p = f / 96;
        int q = f % 96;
        int c = q * 4;
        float4 v = *(const float4*)&base[(size_t)p * 384 + c];
        if (c < 128) {
            v.x *= ATTN_SCALE; v.y *= ATTN_SCALE;
            v.z *= ATTN_SCALE; v.w *= ATTN_SCALE;
            *(float4*)&Qs[p * 132 + c] = v;
        } else if (c < 256) {
            *(float4*)&Ks[p * 132 + c - 128] = v;
        } else {
            *(float4*)&Vs[p * 132 + c - 256] = v;
        }
    }
    __syncthreads();

    {
        int wm = (wid >> 2) * 48, wn = (wid & 3) * 24;
        float acc[3][3][4] = {};
#pragma unroll
        for (int kk = 0; kk < 128; kk += 8) {
            float a[3][4], bf[3][2];
#pragma unroll
            for (int mi = 0; mi < 3; mi++) {
                int r = wm + mi * 16 + gid;
                a[mi][0] = Qs[r * 132 + kk + tig];
                a[mi][1] = Qs[(r + 8) * 132 + kk + tig];
                a[mi][2] = Qs[r * 132 + kk + tig + 4];
                a[mi][3] = Qs[(r + 8) * 132 + kk + tig + 4];
            }
#pragma unroll
            for (int ni = 0; ni < 3; ni++) {
                int c = wn + ni * 8 + gid;
                bf[ni][0] = Ks[c * 132 + kk + tig];
                bf[ni][1] = Ks[c * 132 + kk + tig + 4];
            }
#pragma unroll
            for (int mi = 0; mi < 3; mi++)
#pragma unroll
                for (int ni = 0; ni < 3; ni++)
                    mma8(acc[mi][ni], a[mi], bf[ni]);
        }
#pragma unroll
        for (int mi = 0; mi < 3; mi++)
#pragma unroll
            for (int half = 0; half < 2; half++) {
                int r = wm + mi * 16 + gid + half * 8;
#pragma unroll
                for (int ni = 0; ni < 3; ni++) {
                    int c = wn + ni * 8 + tig * 2;
                    Ss[r * 100 + c] = acc[mi][ni][half * 2 + 0];
                    Ss[r * 100 + c + 1] = acc[mi][ni][half * 2 + 1];
                }
            }
    }
    __syncthreads();

    {
        int w8 = tid >> 5, ln = tid & 31;
        for (int r = w8; r < 96; r += 8) {
            float v0 = Ss[r * 100 + ln];
            float v1 = Ss[r * 100 + 32 + ln];
            float v2 = Ss[r * 100 + 64 + ln];
            float m = fmaxf(v0, fmaxf(v1, v2));
#pragma unroll
            for (int o = 16; o > 0; o >>= 1)
                m = fmaxf(m, __shfl_xor_sync(0xffffffffu, m, o));
            float e0 = expf(v0 - m), e1 = expf(v1 - m), e2 = expf(v2 - m);
            float s = e0 + e1 + e2;
#pragma unroll
            for (int o = 16; o > 0; o >>= 1)
                s += __shfl_xor_sync(0xffffffffu, s, o);
            float inv = 1.0f / s;
            Ss[r * 100 + ln] = e0 * inv;
            Ss[r * 100 + 32 + ln] = e1 * inv;
            Ss[r * 100 + 64 + ln] = e2 * inv;
        }
    }
    __syncthreads();

    {
        int wm = (wid >> 2) * 48, wn = (wid & 3) * 32;
        float acc[3][4][4] = {};
#pragma unroll
        for (int kk = 0; kk < 96; kk += 8) {
            float a[3][4], bf[4][2];
#pragma unroll
            for (int mi = 0; mi < 3; mi++) {
                int r = wm + mi * 16 + gid;
                a[mi][0] = Ss[r * 100 + kk + tig];
                a[mi][1] = Ss[(r + 8) * 100 + kk + tig];
                a[mi][2] = Ss[r * 100 + kk + tig + 4];
                a[mi][3] = Ss[(r + 8) * 100 + kk + tig + 4];
            }
#pragma unroll
            for (int ni = 0; ni < 4; ni++) {
                int c = wn + ni * 8 + gid;
                bf[ni][0] = Vs[(kk + tig) * 132 + c];
                bf[ni][1] = Vs[(kk + tig + 4) * 132 + c];
            }
#pragma unroll
            for (int mi = 0; mi < 3; mi++)
#pragma unroll
                for (int ni = 0; ni < 4; ni++)
                    mma8(acc[mi][ni], a[mi], bf[ni]);
        }
#pragma unroll
        for (int mi = 0; mi < 3; mi++)
#pragma unroll
            for (int half = 0; half < 2; half++) {
                int q = wm + mi * 16 + gid + half * 8;
                int opix = (b * 96 + q) * 96 + h;
#pragma unroll
                for (int ni = 0; ni < 4; ni++) {
                    int c = wn + ni * 8 + tig * 2;
                    *(__half2*)&obufh[(size_t)opix * HDIM + c] =
                        __floats2half2_rn(acc[mi][ni][half * 2 + 0],
                                          acc[mi][ni][half * 2 + 1]);
                }
            }
    }
}

// ---------------------------------------------------------------------------
// MoE top-2 gating + expert index compaction
// ---------------------------------------------------------------------------
__global__ __launch_bounds__(256) void moe_gate_kernel(
    const float* __restrict__ xc, const float* __restrict__ wgf,
    float* __restrict__ mg, int* __restrict__ idx, int* __restrict__ cnt) {
    int gid = blockIdx.x * blockDim.x + threadIdx.x;
    int pix = gid >> 5;
    int lane = gid & 31;
    if (pix >= NPIX) return;
    const float* xp = xc + (size_t)pix * CH;
    float l0 = 0.f, l1 = 0.f, l2 = 0.f;
#pragma unroll
    for (int i = 0; i < 12; i++) {
        int c = i * 32 + lane;
        float xv = xp[c];
        l0 += xv * wgf[c * 3 + 0];
        l1 += xv * wgf[c * 3 + 1];
        l2 += xv * wgf[c * 3 + 2];
    }
#pragma unroll
    for (int o = 16; o > 0; o >>= 1) {
        l0 += __shfl_xor_sync(0xffffffffu, l0, o);
        l1 += __shfl_xor_sync(0xffffffffu, l1, o);
        l2 += __shfl_xor_sync(0xffffffffu, l2, o);
    }
    if (lane == 0) {
        float l[3] = {l0, l1, l2};
        int i0 = 0;
        if (l[1] > l[i0]) i0 = 1;
        if (l[2] > l[i0]) i0 = 2;
        int i1 = -1;
        for (int j = 0; j < 3; j++)
            if (j != i0 && (i1 < 0 || l[j] > l[i1])) i1 = j;
        float e1 = expf(l[i1] - l[i0]);
        float inv = 1.0f / (1.0f + e1);
        float g[3] = {0.f, 0.f, 0.f};
        g[i0] = inv;
        g[i1] = e1 * inv;
        mg[pix * 3 + 0] = g[0];
        mg[pix * 3 + 1] = g[1];
        mg[pix * 3 + 2] = g[2];
        int s0 = atomicAdd(&cnt[i0], 1);
        idx[i0 * NPAD + s0] = pix;
        int s1 = atomicAdd(&cnt[i1], 1);
        idx[i1 * NPAD + s1] = pix;
    }
}

// pad each expert's index list to a multiple of 128 with the dummy row NPIX
__global__ void pad_kernel(const int* __restrict__ cnt, int* __restrict__ idx,
                           int* __restrict__ cntp) {
    int e = blockIdx.x;
    int c = cnt[e];
    int p = (c + 127) & ~127;
    for (int i = c + threadIdx.x; i < p; i += blockDim.x)
        idx[e * NPAD + i] = NPIX;
    if (threadIdx.x == 0) cntp[e] = p;
}

// ---------------------------------------------------------------------------
// Host launcher
// ---------------------------------------------------------------------------
extern "C" void kernel_launch(void* const* d_in, const int* in_sizes, int n_in,
                              void* d_out, int out_size) {
    (void)in_sizes; (void)n_in; (void)out_size;
    const float* x = (const float*)d_in[0];
    const float* w_conv[6] = {(const float*)d_in[1], (const float*)d_in[3],
                              (const float*)d_in[5], (const float*)d_in[7],
                              (const float*)d_in[9], (const float*)d_in[11]};
    const float* b_conv[6] = {(const float*)d_in[2], (const float*)d_in[4],
                              (const float*)d_in[6], (const float*)d_in[8],
                              (const float*)d_in[10], (const float*)d_in[12]};
    const float* wg1 = (const float*)d_in[13];
    const float* wg2 = (const float*)d_in[14];
    const float* wg3 = (const float*)d_in[15];
    const float* w_qkv = (const float*)d_in[16];
    const float* w_ap  = (const float*)d_in[17];
    const float* b_ap  = (const float*)d_in[18];
    const float* wgf   = (const float*)d_in[19];
    const float* w1    = (const float*)d_in[20];
    const float* b1    = (const float*)d_in[21];
    const float* w2    = (const float*)d_in[22];
    const float* b2    = (const float*)d_in[23];
    const float* wp    = (const float*)d_in[24];
    const float* bp    = (const float*)d_in[25];
    float* out = (float*)d_out;

    float *gates, *qkv, *xc, *mgate, *accum;
    int *midx, *cnt, *cntp;
    __half *xh, *wch, *wqkvh, *waph, *w1h, *w2h, *wph;
    __half *moeh, *obufh, *xch, *hiddenh, *accumh;
    cudaGetSymbolAddress((void**)&gates, g_gates);
    cudaGetSymbolAddress((void**)&qkv, g_qkv);
    cudaGetSymbolAddress((void**)&xc, g_xc);
    cudaGetSymbolAddress((void**)&mgate, g_mgate);
    cudaGetSymbolAddress((void**)&accum, g_accum);
    cudaGetSymbolAddress((void**)&midx, g_midx);
    cudaGetSymbolAddress((void**)&cnt, g_cnt);
    cudaGetSymbolAddress((void**)&cntp, g_cntp);
    cudaGetSymbolAddress((void**)&xh, g_xh);
    cudaGetSymbolAddress((void**)&wch, g_wch);
    cudaGetSymbolAddress((void**)&wqkvh, g_wqkvh);
    cudaGetSymbolAddress((void**)&waph, g_waph);
    cudaGetSymbolAddress((void**)&w1h, g_w1h);
    cudaGetSymbolAddress((void**)&w2h, g_w2h);
    cudaGetSymbolAddress((void**)&wph, g_wph);
    cudaGetSymbolAddress((void**)&moeh, g_moeh);
    cudaGetSymbolAddress((void**)&obufh, g_obufh);
    cudaGetSymbolAddress((void**)&xch, g_xch);
    cudaGetSymbolAddress((void**)&hiddenh, g_hiddenh);
    cudaGetSymbolAddress((void**)&accumh, g_accumh);

    cudaFuncSetAttribute(attn_tc, cudaFuncAttributeMaxDynamicSharedMemorySize,
                         ATTN_SMEM_BYTES);
    cudaFuncSetAttribute(conv_moe_h, cudaFuncAttributeMaxDynamicSharedMemorySize,
                         CONVH_SMEM_BYTES);
    cudaFuncSetAttribute(gemm_h, cudaFuncAttributeMaxDynamicSharedMemorySize,
                         GH_SMEM_BYTES);

    auto f2h = [](const float* s, __half* d, size_t n) {
        int n4 = (int)(n / 4);
        f2h_kernel<<<(n4 + 255) / 256, 256>>>(s, d, n4);
    };

    // reset routing state + output accumulator
    cudaMemsetAsync(cnt, 0, 3 * sizeof(int));
    cudaMemsetAsync(accum, 0, (size_t)NPIX * CH * sizeof(float));

    // 0. fp16 conversions (weights + input)
    f2h(x, xh, (size_t)NPIX * CH);
    for (int i = 0; i < 6; i++)
        f2h(w_conv[i], wch + (size_t)i * 9 * 128 * 128, 9 * 128 * 128);
    f2h(w_qkv, wqkvh, 3 * 128 * 384);
    f2h(w_ap, waph, 3 * 128 * 128);
    f2h(w1, w1h, (size_t)3 * 384 * 1536);
    f2h(w2, w2h, (size_t)3 * 1536 * 384);
    f2h(wp, wph, 384 * 384);

    // 1. per-branch 2-way gates
    branch_gate_kernel<<<NPIX / 8, 256>>>(x, wg1, wg2, wg3, gates);

    // 2. branches
    for (int br = 0; br < 3; br++) {
        conv_moe_h<<<dim3(3 * HGT, BATCH), 256, CONVH_SMEM_BYTES>>>(
            xh, wch + (size_t)(2 * br) * 9 * 128 * 128, b_conv[2 * br],
            wch + (size_t)(2 * br + 1) * 9 * 128 * 128, b_conv[2 * br + 1],
            gates, br, moeh);
        gemm_h<<<dim3((3 * HDIM) / 128, NPIX / 128), 256, GH_SMEM_BYTES>>>(
            moeh, HDIM, wqkvh + (size_t)br * HDIM * 3 * HDIM, 3 * HDIM,
            nullptr, nullptr, 0, 0, qkv, nullptr, 3 * HDIM, HDIM, 0, 0,
            nullptr, 0, nullptr);
        attn_tc<<<BATCH * HGT, 256, ATTN_SMEM_BYTES>>>(qkv, obufh);
        gemm_h<<<dim3(HDIM / 128, NPIX / 128), 256, GH_SMEM_BYTES>>>(
            obufh, HDIM, waph + (size_t)br * HDIM * HDIM, HDIM,
            b_ap + (size_t)br * HDIM, nullptr, 0, 0,
            xc + br * HDIM, xch + br * HDIM, CH, HDIM, 0, 0,
            nullptr, 0, nullptr);
    }

    // 3. top-2 MoE gates + compaction + padding
    moe_gate_kernel<<<NPIX / 8, 256>>>(xc, wgf, mgate, midx, cnt);
    pad_kernel<<<3, 128>>>(cnt, midx, cntp);

    // 4. sparse 2-of-3 expert MLP (gather rows -> hidden; scatter-accum out)
    for (int e = 0; e < 3; e++) {
        gemm_h<<<dim3(MLPH / 128, NPIX / 128), 256, GH_SMEM_BYTES>>>(
            xch, CH, w1h + (size_t)e * CH * MLPH, MLPH, b1 + (size_t)e * MLPH,
            nullptr, 0, 0, nullptr, hiddenh, MLPH, CH, 1, 0,
            midx + e * NPAD, 1, cntp + e);
        gemm_h<<<dim3(CH / 128, NPIX / 128), 256, GH_SMEM_BYTES>>>(
            hiddenh, MLPH, w2h + (size_t)e * MLPH * CH, CH, b2 + (size_t)e * CH,
            mgate, 3, e, accum, nullptr, CH, MLPH, 0, 1,
            midx + e * NPAD, 0, cntp + e);
    }

    // 5. final projection (accum -> fp16 -> out)
    f2h(accum, accumh, (size_t)NPIX * CH);
    gemm_h<<<dim3(CH / 128, NPIX / 128), 256, GH_SMEM_BYTES>>>(
        accumh, CH, wph, CH, bp, nullptr, 0, 0, out, nullptr, CH, CH, 0, 0,
        nullptr, 0, nullptr);
}